// round 2
// baseline (speedup 1.0000x reference)
#include <cuda_runtime.h>
#include <math.h>

#define NIMG 48            // B*C = 16*3
#define NBATCH 16
#define N 1024
#define OUT_HW 224
// antialiased triangle kernel: support radius = inv_scale = 1024/224
#define KRAD (1024.0f/224.0f)
#define KSCL (224.0f/1024.0f)

// scratch (static device arrays; no allocation allowed)
__device__ float2 g_A[(size_t)NIMG * N * N];        // row-FFT output [img][y][kx]
__device__ float2 g_B[(size_t)NIMG * N * N];        // transposed     [img][kx][y]
__device__ float  g_T[(size_t)NIMG * N * OUT_HW];   // ky-resized     [img][kxs][oy]
__device__ unsigned int g_mn[NBATCH];
__device__ unsigned int g_mx[NBATCH];

__device__ __forceinline__ float2 cmul(float2 a, float2 b) {
    return make_float2(a.x*b.x - a.y*b.y, a.x*b.y + a.y*b.x);
}
__device__ __forceinline__ float2 cadd(float2 a, float2 b){ return make_float2(a.x+b.x, a.y+b.y); }
__device__ __forceinline__ float2 csub(float2 a, float2 b){ return make_float2(a.x-b.x, a.y-b.y); }

// base-4 digit reversal of a 10-bit index (1024 = 4^5)
__device__ __forceinline__ int rev4_10(int i) {
    return ((i & 3) << 8) | ((i & 12) << 4) | (i & 48) | ((i >> 4) & 12) | ((i >> 8) & 3);
}

// twiddle table tw[j] = exp(-2*pi*i*j/1024), j in [0,768)
__device__ __forceinline__ void fill_tw(float2* tw, int tid) {
    for (int j = tid; j < 768; j += 256) {
        float s, c;
        sincosf(-6.283185307179586f * (float)j / 1024.0f, &s, &c);
        tw[j] = make_float2(c, s);
    }
}

// in-place radix-4 DIT FFT, 1024 points, input digit-reversed. 256 threads.
__device__ __forceinline__ void fft1024_r4(float2* s, const float2* tw, int tid) {
    #pragma unroll
    for (int st = 0; st < 5; ++st) {
        int quarter = 1 << (2*st);
        int pos  = tid & (quarter - 1);
        int base = ((tid - pos) << 2) + pos;
        int tstep = 256 >> (2*st);           // N/len
        float2 x0 = s[base];
        float2 x1 = s[base + quarter];
        float2 x2 = s[base + 2*quarter];
        float2 x3 = s[base + 3*quarter];
        if (st) {
            int ti = pos * tstep;
            x1 = cmul(tw[ti],     x1);
            x2 = cmul(tw[2*ti],   x2);
            x3 = cmul(tw[3*ti],   x3);
        }
        float2 u0 = cadd(x0, x2);
        float2 u1 = csub(x0, x2);
        float2 u2 = cadd(x1, x3);
        float2 u3 = csub(x1, x3);
        s[base]             = cadd(u0, u2);
        s[base + quarter]   = make_float2(u1.x + u3.y, u1.y - u3.x); // u1 - i*u3
        s[base + 2*quarter] = csub(u0, u2);
        s[base + 3*quarter] = make_float2(u1.x - u3.y, u1.y + u3.x); // u1 + i*u3
        __syncthreads();
    }
}

__global__ void k_init(void) {
    int t = threadIdx.x;
    if (t < NBATCH) { g_mn[t] = 0x7f800000u; g_mx[t] = 0u; }
}

__global__ void __launch_bounds__(256) k_rowfft(const float* __restrict__ in) {
    __shared__ float2 s[N];
    __shared__ float2 tw[768];
    int row = blockIdx.x;               // img*1024 + y
    int tid = threadIdx.x;
    fill_tw(tw, tid);
    const float* rp = in + (size_t)row * N;
    #pragma unroll
    for (int e = tid; e < N; e += 256)
        s[rev4_10(e)] = make_float2(rp[e], 0.0f);
    __syncthreads();
    fft1024_r4(s, tw, tid);
    float2* op = g_A + (size_t)row * N;
    #pragma unroll
    for (int e = tid; e < N; e += 256)
        op[e] = s[e];
}

__global__ void k_transpose(void) {
    __shared__ float2 tile[32][33];
    size_t imgoff = (size_t)blockIdx.z * N * N;
    int x0 = blockIdx.x * 32, y0 = blockIdx.y * 32;
    int tx = threadIdx.x, ty = threadIdx.y;
    #pragma unroll
    for (int dy = ty; dy < 32; dy += 8)
        tile[dy][tx] = g_A[imgoff + (size_t)(y0 + dy) * N + x0 + tx];
    __syncthreads();
    #pragma unroll
    for (int dy = ty; dy < 32; dy += 8)
        g_B[imgoff + (size_t)(x0 + dy) * N + y0 + tx] = tile[tx][dy];
}

__global__ void __launch_bounds__(256) k_colfft(void) {
    __shared__ float2 s[N];
    __shared__ float2 tw[768];
    __shared__ float  m[N];             // shifted log-magnitude over kys
    __shared__ float  rmn[8], rmx[8];
    int blk = blockIdx.x;               // img*1024 + kx
    int img = blk >> 10;
    int kx  = blk & (N - 1);
    int tid = threadIdx.x;
    fill_tw(tw, tid);
    const float2* cp = g_B + (size_t)blk * N;
    #pragma unroll
    for (int e = tid; e < N; e += 256)
        s[rev4_10(e)] = cp[e];
    __syncthreads();
    fft1024_r4(s, tw, tid);

    float mn = 3.4e38f, mx = 0.0f;
    #pragma unroll
    for (int e = tid; e < N; e += 256) {
        float2 v = s[e];
        float mag = log1pf(sqrtf(v.x*v.x + v.y*v.y));
        m[(e + 512) & (N - 1)] = mag;   // fftshift along ky
        mn = fminf(mn, mag); mx = fmaxf(mx, mag);
    }
    #pragma unroll
    for (int o = 16; o; o >>= 1) {
        mn = fminf(mn, __shfl_xor_sync(0xffffffffu, mn, o));
        mx = fmaxf(mx, __shfl_xor_sync(0xffffffffu, mx, o));
    }
    if ((tid & 31) == 0) { rmn[tid >> 5] = mn; rmx[tid >> 5] = mx; }
    __syncthreads();                    // also fences m[] for resize reads
    if (tid == 0) {
        float a = rmn[0], c = rmx[0];
        #pragma unroll
        for (int w = 1; w < 8; ++w) { a = fminf(a, rmn[w]); c = fmaxf(c, rmx[w]); }
        int b = img / 3;                // img = b*3 + channel
        atomicMin(&g_mn[b], __float_as_uint(a));
        atomicMax(&g_mx[b], __float_as_uint(c));
    }

    // antialiased triangle resize along kys (weights sum normalized, matches jax)
    if (tid < OUT_HW) {
        int kxs = (kx + 512) & (N - 1); // fftshift along kx
        float sf = ((float)tid + 0.5f) * (1024.0f/224.0f) - 0.5f;
        int i0 = max(0, (int)ceilf(sf - KRAD));
        int i1 = min(N - 1, (int)floorf(sf + KRAD));
        float acc = 0.0f, sw = 0.0f;
        for (int i = i0; i <= i1; ++i) {
            float w = fmaxf(0.0f, 1.0f - fabsf(sf - (float)i) * KSCL);
            acc += w * m[i]; sw += w;
        }
        g_T[((size_t)img * N + kxs) * OUT_HW + tid] = acc / sw;
    }
}

__global__ void __launch_bounds__(224) k_resize2(float* __restrict__ out) {
    int blk = blockIdx.x;               // img*224 + ox
    int img = blk / OUT_HW;
    int ox  = blk - img * OUT_HW;
    int oy  = threadIdx.x;
    float sf = ((float)ox + 0.5f) * (1024.0f/224.0f) - 0.5f;
    int i0 = max(0, (int)ceilf(sf - KRAD));
    int i1 = min(N - 1, (int)floorf(sf + KRAD));
    float acc = 0.0f, sw = 0.0f;
    const float* base = g_T + (size_t)img * N * OUT_HW + oy;
    for (int i = i0; i <= i1; ++i) {
        float w = fmaxf(0.0f, 1.0f - fabsf(sf - (float)i) * KSCL);
        acc += w * base[(size_t)i * OUT_HW]; sw += w;
    }
    int b = img / 3;
    float mn = __uint_as_float(g_mn[b]);
    float mx = __uint_as_float(g_mx[b]);
    float v = (acc / sw - mn) / (mx - mn + 1e-8f);
    out[((size_t)img * OUT_HW + oy) * OUT_HW + ox] = v;
}

extern "C" void kernel_launch(void* const* d_in, const int* in_sizes, int n_in,
                              void* d_out, int out_size) {
    (void)in_sizes; (void)n_in; (void)out_size;
    const float* in = (const float*)d_in[0];
    float* out = (float*)d_out;

    k_init<<<1, 32>>>();
    k_rowfft<<<NIMG * N, 256>>>(in);
    dim3 tg(N / 32, N / 32, NIMG), tb(32, 8);
    k_transpose<<<tg, tb>>>();
    k_colfft<<<NIMG * N, 256>>>();
    k_resize2<<<NIMG * OUT_HW, 224>>>(out);
}